// round 4
// baseline (speedup 1.0000x reference)
#include <cuda_runtime.h>

// Problem constants
#define BB 16
#define NN 4096
#define DD 256
#define KK 512
#define MM (BB * NN)            // 65536 positions
#define COMMIT_W 0.25f

// Scratch (device globals: no allocation allowed)
__device__ float  g_esq[KK];
__device__ int    g_best[MM];
__device__ double g_loss;

// ---------------------------------------------------------------------------
// Kernel 0: precompute ||e_k||^2 and zero the loss accumulator.
// ---------------------------------------------------------------------------
__global__ void prep_kernel(const float* __restrict__ cb) {
    int k = blockIdx.x * blockDim.x + threadIdx.x;
    if (k == 0) g_loss = 0.0;
    if (k < KK) {
        const float4* row = (const float4*)(cb + (size_t)k * DD);
        float s = 0.f;
#pragma unroll 16
        for (int i = 0; i < DD / 4; i++) {
            float4 v = row[i];
            s += v.x * v.x + v.y * v.y + v.z * v.z + v.w * v.w;
        }
        g_esq[k] = s;
    }
}

// ---------------------------------------------------------------------------
// Kernel 1: fused cross-GEMM + argmin.
// CTA: 256 threads (tm 0..15, tk 0..15). Tile: 64 rows x all 512 codes.
// Inner: 64-code chunk x 64-d chunk, 4x4 register fragments.
// dist_k = ||e_k||^2 - 2 * <z, e_k>   (||z||^2 dropped: constant per row)
// ---------------------------------------------------------------------------
__global__ void __launch_bounds__(256, 2) argmin_kernel(
    const float* __restrict__ z, const float* __restrict__ cb)
{
    __shared__ float zs[64][64];   // [d][m]
    __shared__ float cs[64][64];   // [d][k]
    __shared__ float redv[64][17];
    __shared__ int   redi[64][17];

    const int tid = threadIdx.x;
    const int tm  = tid & 15;      // row-fragment index
    const int tk  = tid >> 4;      // code-fragment index
    const int row0 = blockIdx.x * 64;

    // tile-load mapping: lm = row/code within tile, lq picks 16-d segment
    const int lm = tid & 63;
    const int lq = tid >> 6;       // 0..3

    float bestv[4];
    int   besti[4];
#pragma unroll
    for (int i = 0; i < 4; i++) { bestv[i] = 3.4e38f; besti[i] = 0; }

    for (int kc = 0; kc < KK; kc += 64) {
        float acc[4][4];
#pragma unroll
        for (int i = 0; i < 4; i++)
#pragma unroll
            for (int j = 0; j < 4; j++) acc[i][j] = 0.f;

        for (int dc = 0; dc < DD; dc += 64) {
            __syncthreads();   // protect smem from previous iteration's readers
            // load z tile (transposed into [d][m])
            {
                const float4* zp = (const float4*)(z + (size_t)(row0 + lm) * DD + dc + lq * 16);
#pragma unroll
                for (int i = 0; i < 4; i++) {
                    float4 v = zp[i];
                    int d = lq * 16 + i * 4;
                    zs[d + 0][lm] = v.x; zs[d + 1][lm] = v.y;
                    zs[d + 2][lm] = v.z; zs[d + 3][lm] = v.w;
                }
            }
            // load codebook tile (transposed into [d][k])
            {
                const float4* cp = (const float4*)(cb + (size_t)(kc + lm) * DD + dc + lq * 16);
#pragma unroll
                for (int i = 0; i < 4; i++) {
                    float4 v = cp[i];
                    int d = lq * 16 + i * 4;
                    cs[d + 0][lm] = v.x; cs[d + 1][lm] = v.y;
                    cs[d + 2][lm] = v.z; cs[d + 3][lm] = v.w;
                }
            }
            __syncthreads();

#pragma unroll 16
            for (int d = 0; d < 64; d++) {
                float4 za = *(const float4*)&zs[d][tm * 4];
                float4 ca = *(const float4*)&cs[d][tk * 4];
                float zr[4] = { za.x, za.y, za.z, za.w };
                float cr[4] = { ca.x, ca.y, ca.z, ca.w };
#pragma unroll
                for (int i = 0; i < 4; i++)
#pragma unroll
                    for (int j = 0; j < 4; j++)
                        acc[i][j] += zr[i] * cr[j];
            }
        }

        // fold into running argmin (indices visited ascending; strict < keeps first)
#pragma unroll
        for (int j = 0; j < 4; j++) {
            int kidx = kc + tk * 4 + j;
            float es = g_esq[kidx];
#pragma unroll
            for (int i = 0; i < 4; i++) {
                float dist = fmaf(-2.f, acc[i][j], es);
                if (dist < bestv[i]) { bestv[i] = dist; besti[i] = kidx; }
            }
        }
    }

    // cross-thread (tk) reduction per row; lower index wins ties
    __syncthreads();
#pragma unroll
    for (int i = 0; i < 4; i++) {
        redv[tm * 4 + i][tk] = bestv[i];
        redi[tm * 4 + i][tk] = besti[i];
    }
    __syncthreads();
    if (tid < 64) {
        float bv = redv[tid][0];
        int   bi = redi[tid][0];
#pragma unroll
        for (int t = 1; t < 16; t++) {
            float v = redv[tid][t];
            int   ix = redi[tid][t];
            if (v < bv || (v == bv && ix < bi)) { bv = v; bi = ix; }
        }
        g_best[row0 + tid] = bi;
    }
}

// ---------------------------------------------------------------------------
// Kernel 2: gather + mask + loss accumulation. One warp per position.
// Mask is read as 32-bit words: nonzero == true. This is correct whether the
// harness materialized the bool array as int32 (1/0) or float32 (1.0f/0.0f).
// ---------------------------------------------------------------------------
__global__ void __launch_bounds__(256) quant_kernel(
    const float* __restrict__ z, const unsigned int* __restrict__ mask,
    const float* __restrict__ cb, float* __restrict__ outq,
    float* __restrict__ outi)
{
    __shared__ float wsum[8];
    const int warp = threadIdx.x >> 5;
    const int lane = threadIdx.x & 31;
    const int pos  = blockIdx.x * 8 + warp;

    const int idx = g_best[pos];
    const bool mk = (mask[pos] != 0u);
    const float m = mk ? 1.f : 0.f;
    const float4* zp = (const float4*)(z  + (size_t)pos * DD);
    const float4* ep = (const float4*)(cb + (size_t)idx * DD);
    float4* op = (float4*)(outq + (size_t)pos * DD);

    float s = 0.f;
#pragma unroll
    for (int i = lane; i < DD / 4; i += 32) {
        float4 zv = zp[i];
        float4 ev = ep[i];
        float dx = ev.x - zv.x, dy = ev.y - zv.y,
              dz = ev.z - zv.z, dw = ev.w - zv.w;
        s += dx * dx + dy * dy + dz * dz + dw * dw;
        op[i] = make_float4(ev.x * m, ev.y * m, ev.z * m, ev.w * m);
    }
    if (lane == 0) outi[pos] = mk ? (float)idx : -1.0f;

    // warp reduce
#pragma unroll
    for (int off = 16; off > 0; off >>= 1)
        s += __shfl_down_sync(0xFFFFFFFFu, s, off);
    if (lane == 0) wsum[warp] = s;
    __syncthreads();
    if (threadIdx.x == 0) {
        float b = 0.f;
#pragma unroll
        for (int w = 0; w < 8; w++) b += wsum[w];
        atomicAdd(&g_loss, (double)b);
    }
}

// ---------------------------------------------------------------------------
// Kernel 3: finalize commit loss.
// ---------------------------------------------------------------------------
__global__ void finalize_kernel(float* __restrict__ out_loss) {
    out_loss[0] = (float)(COMMIT_W * g_loss / ((double)MM * (double)DD));
}

// ---------------------------------------------------------------------------
extern "C" void kernel_launch(void* const* d_in, const int* in_sizes, int n_in,
                              void* d_out, int out_size) {
    const float*        z    = (const float*)d_in[0];
    const unsigned int* mask = (const unsigned int*)d_in[1];
    const float*        cb   = (const float*)d_in[2];

    float* outq = (float*)d_out;                         // (B,N,D)
    float* outi = outq + (size_t)MM * DD;                // (B,N) indices as float
    float* outl = outi + MM;                             // scalar loss

    prep_kernel<<<1, 512>>>(cb);
    argmin_kernel<<<MM / 64, 256>>>(z, cb);
    quant_kernel<<<MM / 8, 256>>>(z, mask, cb, outq, outi);
    finalize_kernel<<<1, 1>>>(outl);
}